// round 2
// baseline (speedup 1.0000x reference)
#include <cuda_runtime.h>
#include <cstdint>
#include <cstddef>

#define NROW 4096
#define DIM  512
#define R2   8192          // 2N
#define THR  409           // int(4096 * 0.1)

// ---------------- device scratch (no allocations allowed) ----------------
static __device__ float g_Z[(size_t)R2 * DIM];        // 16 MB normalized rows
static __device__ float g_S[(size_t)R2 * R2];         // 256 MB Gram matrix
static __device__ float g_logneg[R2];

// ---------------- helpers ----------------
// exp(2x) via exp2, FMA-only (avoid MUFU throughput wall on 67M exps)
__device__ __forceinline__ float fast_exp2x(float x) {
    float y = x * 2.885390081777927f;       // 2*log2(e)*x
    float n = rintf(y);
    float r = y - n;                        // r in [-0.5, 0.5]
    float p = 1.5403530393381609e-4f;       // poly for 2^r = exp(r*ln2)
    p = fmaf(p, r, 1.3333558146428443e-3f);
    p = fmaf(p, r, 9.6181291076284772e-3f);
    p = fmaf(p, r, 5.5504108664821580e-2f);
    p = fmaf(p, r, 2.4022650695910071e-1f);
    p = fmaf(p, r, 6.9314718055994531e-1f);
    p = fmaf(p, r, 1.0f);
    int e = (int)n;                         // |e| <= 5
    float s = __int_as_float((e + 127) << 23);
    return p * s;
}

// order-preserving float <-> uint key
__device__ __forceinline__ unsigned f2k(float x) {
    unsigned u = __float_as_uint(x);
    return (u & 0x80000000u) ? ~u : (u | 0x80000000u);
}
__device__ __forceinline__ float k2f(unsigned k) {
    return (k & 0x80000000u) ? __uint_as_float(k ^ 0x80000000u)
                             : __uint_as_float(~k);
}

__device__ __forceinline__ float blockReduce256(float v, float* red8) {
    int tid = threadIdx.x;
    #pragma unroll
    for (int off = 16; off; off >>= 1) v += __shfl_down_sync(0xffffffffu, v, off);
    if ((tid & 31) == 0) red8[tid >> 5] = v;
    __syncthreads();
    if (tid == 0) {
        float t = 0.f;
        #pragma unroll
        for (int w = 0; w < 8; w++) t += red8[w];
        red8[0] = t;
    }
    __syncthreads();
    float r = red8[0];
    __syncthreads();
    return r;
}

// ---------------- kernel 1: row L2 normalize ----------------
__global__ void k_normalize(const float* __restrict__ h1, const float* __restrict__ h2) {
    int r = blockIdx.x;                    // 0 .. 8191
    const float* src = (r < NROW) ? (h1 + (size_t)r * DIM)
                                  : (h2 + (size_t)(r - NROW) * DIM);
    int tid = threadIdx.x;                 // 128 threads, 4 floats each
    float4 v = ((const float4*)src)[tid];
    float ss = v.x * v.x + v.y * v.y + v.z * v.z + v.w * v.w;
    __shared__ float red[8];
    #pragma unroll
    for (int off = 16; off; off >>= 1) ss += __shfl_down_sync(0xffffffffu, ss, off);
    if ((tid & 31) == 0) red[tid >> 5] = ss;
    __syncthreads();
    if (tid == 0) {
        float t = red[0] + red[1] + red[2] + red[3];
        red[0] = 1.0f / fmaxf(sqrtf(t), 1e-12f);
    }
    __syncthreads();
    float rinv = red[0];
    float4 o = make_float4(v.x * rinv, v.y * rinv, v.z * rinv, v.w * rinv);
    ((float4*)(g_Z + (size_t)r * DIM))[tid] = o;
}

// ---------------- kernel 2: S = Z * Z^T (fp32 SIMT SGEMM) ----------------
// 128x128 tile, BK=16, 256 threads, 8x8 micro-tile per thread
__global__ void __launch_bounds__(256) k_gemm() {
    __shared__ float As[16][132];
    __shared__ float Bs[16][132];
    const int tid = threadIdx.x;
    const int bm = blockIdx.y * 128;
    const int bn = blockIdx.x * 128;
    const int tx = tid & 15, ty = tid >> 4;

    float acc[8][8];
    #pragma unroll
    for (int i = 0; i < 8; i++)
        #pragma unroll
        for (int j = 0; j < 8; j++) acc[i][j] = 0.f;

    for (int k0 = 0; k0 < DIM; k0 += 16) {
        #pragma unroll
        for (int i = 0; i < 2; i++) {
            int id  = tid + i * 256;        // 0..511
            int row = id >> 2;
            int kc  = (id & 3) << 2;
            float4 a = *(const float4*)(g_Z + (size_t)(bm + row) * DIM + k0 + kc);
            As[kc + 0][row] = a.x; As[kc + 1][row] = a.y;
            As[kc + 2][row] = a.z; As[kc + 3][row] = a.w;
            float4 b = *(const float4*)(g_Z + (size_t)(bn + row) * DIM + k0 + kc);
            Bs[kc + 0][row] = b.x; Bs[kc + 1][row] = b.y;
            Bs[kc + 2][row] = b.z; Bs[kc + 3][row] = b.w;
        }
        __syncthreads();
        #pragma unroll
        for (int kk = 0; kk < 16; kk++) {
            float4 aA = *(const float4*)&As[kk][ty * 8];
            float4 aB = *(const float4*)&As[kk][ty * 8 + 4];
            float4 bA = *(const float4*)&Bs[kk][tx * 8];
            float4 bB = *(const float4*)&Bs[kk][tx * 8 + 4];
            float a[8] = {aA.x, aA.y, aA.z, aA.w, aB.x, aB.y, aB.z, aB.w};
            float b[8] = {bA.x, bA.y, bA.z, bA.w, bB.x, bB.y, bB.z, bB.w};
            #pragma unroll
            for (int i = 0; i < 8; i++)
                #pragma unroll
                for (int j = 0; j < 8; j++)
                    acc[i][j] = fmaf(a[i], b[j], acc[i][j]);
        }
        __syncthreads();
    }

    #pragma unroll
    for (int i = 0; i < 8; i++) {
        size_t p = (size_t)(bm + ty * 8 + i) * R2 + bn + tx * 8;
        *(float4*)(g_S + p)     = make_float4(acc[i][0], acc[i][1], acc[i][2], acc[i][3]);
        *(float4*)(g_S + p + 4) = make_float4(acc[i][4], acc[i][5], acc[i][6], acc[i][7]);
    }
}

// ---------------- kernel 3: per-row trim + exp-sum (exact radix select) ----------------
__global__ void __launch_bounds__(256) k_select() {
    const int r   = blockIdx.x;
    const int tid = threadIdx.x;     // 256 threads
    __shared__ unsigned su[R2];      // 32 KB row keys
    __shared__ unsigned hist[256];
    __shared__ unsigned sc[256];
    __shared__ float    redf[8];
    __shared__ unsigned s_sel, s_k;

    const float* row = g_S + (size_t)r * R2;
    float tot = 0.f;
    #pragma unroll
    for (int j = 0; j < 8; j++) {
        int i4 = tid + j * 256;                 // 0..2047 float4s
        float4 v = ((const float4*)row)[i4];
        tot += fast_exp2x(v.x) + fast_exp2x(v.y) + fast_exp2x(v.z) + fast_exp2x(v.w);
        su[i4 * 4 + 0] = f2k(v.x);
        su[i4 * 4 + 1] = f2k(v.y);
        su[i4 * 4 + 2] = f2k(v.z);
        su[i4 * 4 + 3] = f2k(v.w);
    }
    tot = blockReduce256(tot, redf);            // also fences su stores

    // ---- radix select: 409th-largest key ----
    unsigned prefix = 0, mask = 0, k = THR;
    #pragma unroll
    for (int pass = 0; pass < 4; pass++) {
        int shift = 24 - 8 * pass;
        hist[tid] = 0; __syncthreads();
        for (int i = tid; i < R2; i += 256) {
            unsigned key = su[i];
            if ((key & mask) == prefix) atomicAdd(&hist[(key >> shift) & 255u], 1u);
        }
        __syncthreads();
        sc[tid] = hist[tid]; __syncthreads();
        for (int off = 1; off < 256; off <<= 1) {   // inclusive suffix scan
            unsigned add = (tid + off < 256) ? sc[tid + off] : 0u;
            __syncthreads();
            sc[tid] += add;
            __syncthreads();
        }
        unsigned ge = sc[tid];
        unsigned gt = (tid < 255) ? sc[tid + 1] : 0u;
        if (ge >= k && gt < k) { s_sel = (unsigned)tid; s_k = k - gt; }
        __syncthreads();
        prefix |= s_sel << shift;
        mask   |= 255u  << shift;
        k = s_k;
        __syncthreads();
    }
    const unsigned Khi = prefix, dup_hi = k;

    // ---- radix select: 409th-smallest key ----
    prefix = 0; mask = 0; k = THR;
    #pragma unroll
    for (int pass = 0; pass < 4; pass++) {
        int shift = 24 - 8 * pass;
        hist[tid] = 0; __syncthreads();
        for (int i = tid; i < R2; i += 256) {
            unsigned key = su[i];
            if ((key & mask) == prefix) atomicAdd(&hist[(key >> shift) & 255u], 1u);
        }
        __syncthreads();
        sc[tid] = hist[tid]; __syncthreads();
        for (int off = 1; off < 256; off <<= 1) {   // inclusive prefix scan
            unsigned add = (tid >= off) ? sc[tid - off] : 0u;
            __syncthreads();
            sc[tid] += add;
            __syncthreads();
        }
        unsigned le = sc[tid];
        unsigned lt = (tid > 0) ? sc[tid - 1] : 0u;
        if (le >= k && lt < k) { s_sel = (unsigned)tid; s_k = k - lt; }
        __syncthreads();
        prefix |= s_sel << shift;
        mask   |= 255u  << shift;
        k = s_k;
        __syncthreads();
    }
    const unsigned Klo = prefix, dup_lo = k;

    // ---- tail sums (exact, tie-correct) ----
    float ts = 0.f, bs = 0.f;
    for (int i = tid; i < R2; i += 256) {
        unsigned key = su[i];
        if (key > Khi) ts += fast_exp2x(k2f(key));
        if (key < Klo) bs += fast_exp2x(k2f(key));
    }
    ts = blockReduce256(ts, redf);
    bs = blockReduce256(bs, redf);

    if (tid == 0) {
        float top = ts + (float)dup_hi * fast_exp2x(k2f(Khi));
        float bot = bs + (float)dup_lo * fast_exp2x(k2f(Klo));
        g_logneg[r] = logf(tot - top - bot);
    }
}

// ---------------- kernel 4: final scalar ----------------
__global__ void k_final(float* __restrict__ out) {
    int tid = threadIdx.x;   // 256
    double sl = 0.0, sd = 0.0;
    for (int i = tid; i < R2; i += 256) sl += (double)g_logneg[i];
    for (int i = tid; i < NROW; i += 256) sd += (double)g_S[(size_t)i * R2 + NROW + i];
    __shared__ double rd[256];
    rd[tid] = sl; __syncthreads();
    for (int off = 128; off; off >>= 1) {
        if (tid < off) rd[tid] += rd[tid + off];
        __syncthreads();
    }
    double SL = rd[0]; __syncthreads();
    rd[tid] = sd; __syncthreads();
    for (int off = 128; off; off >>= 1) {
        if (tid < off) rd[tid] += rd[tid + off];
        __syncthreads();
    }
    double SD = rd[0];
    if (tid == 0)
        out[0] = (float)(0.5 * SL / (double)NROW - 2.0 * SD / (double)NROW);
}

// ---------------- launch ----------------
extern "C" void kernel_launch(void* const* d_in, const int* in_sizes, int n_in,
                              void* d_out, int out_size) {
    const float* h1 = (const float*)d_in[0];
    const float* h2 = (const float*)d_in[1];
    (void)in_sizes; (void)n_in; (void)out_size;

    k_normalize<<<R2, 128>>>(h1, h2);
    dim3 g(R2 / 128, R2 / 128);
    k_gemm<<<g, 256>>>();
    k_select<<<R2, 256>>>();
    k_final<<<1, 256>>>((float*)d_out);
}

// round 5
// speedup vs baseline: 3.3630x; 3.3630x over previous
#include <cuda_runtime.h>
#include <cuda_bf16.h>
#include <cstdint>
#include <cstddef>

#define NROW 4096
#define DIM  512
#define R2   8192          // 2N
#define THR  409           // int(4096 * 0.1)

// ---------------- device scratch (no allocations allowed) ----------------
static __device__ __nv_bfloat16 g_Zb[(size_t)R2 * DIM];   // 8 MB normalized rows (bf16)
static __device__ float g_S[(size_t)R2 * R2];             // 256 MB Gram matrix
static __device__ double g_acc;

// ================= PTX helpers (base ISA only: sm_80+) =================
__device__ __forceinline__ uint32_t smem_u32(const void* p) {
    uint32_t a;
    asm("{ .reg .u64 t; cvta.to.shared.u64 t, %1; cvt.u32.u64 %0, t; }" : "=r"(a) : "l"(p));
    return a;
}
__device__ __forceinline__ void cp_async16(uint32_t saddr, const void* gptr) {
    asm volatile("cp.async.cg.shared.global [%0], [%1], 16;\n" :: "r"(saddr), "l"(gptr));
}
__device__ __forceinline__ void cp_commit() {
    asm volatile("cp.async.commit_group;\n" ::: "memory");
}
template <int N>
__device__ __forceinline__ void cp_wait() {
    asm volatile("cp.async.wait_group %0;\n" :: "n"(N) : "memory");
}
__device__ __forceinline__ void ldm_x4(uint32_t addr, uint32_t& r0, uint32_t& r1,
                                       uint32_t& r2, uint32_t& r3) {
    asm volatile("ldmatrix.sync.aligned.m8n8.x4.shared.b16 {%0,%1,%2,%3}, [%4];\n"
                 : "=r"(r0), "=r"(r1), "=r"(r2), "=r"(r3) : "r"(addr));
}
__device__ __forceinline__ void mma_bf16(float& d0, float& d1, float& d2, float& d3,
                                         uint32_t a0, uint32_t a1, uint32_t a2, uint32_t a3,
                                         uint32_t b0, uint32_t b1) {
    asm volatile("mma.sync.aligned.m16n8k16.row.col.f32.bf16.bf16.f32 "
                 "{%0,%1,%2,%3}, {%4,%5,%6,%7}, {%8,%9}, {%0,%1,%2,%3};\n"
                 : "+f"(d0), "+f"(d1), "+f"(d2), "+f"(d3)
                 : "r"(a0), "r"(a1), "r"(a2), "r"(a3), "r"(b0), "r"(b1));
}

// ---------------- math helpers ----------------
__device__ __forceinline__ float fast_exp2x(float x) {
    float y = x * 2.885390081777927f;       // 2*log2(e)*x
    float n = rintf(y);
    float r = y - n;
    float p = 1.5403530393381609e-4f;
    p = fmaf(p, r, 1.3333558146428443e-3f);
    p = fmaf(p, r, 9.6181291076284772e-3f);
    p = fmaf(p, r, 5.5504108664821580e-2f);
    p = fmaf(p, r, 2.4022650695910071e-1f);
    p = fmaf(p, r, 6.9314718055994531e-1f);
    p = fmaf(p, r, 1.0f);
    int e = (int)n;
    float s = __int_as_float((e + 127) << 23);
    return p * s;
}
__device__ __forceinline__ unsigned f2k(float x) {
    unsigned u = __float_as_uint(x);
    return (u & 0x80000000u) ? ~u : (u | 0x80000000u);
}
__device__ __forceinline__ float k2f(unsigned k) {
    return (k & 0x80000000u) ? __uint_as_float(k ^ 0x80000000u) : __uint_as_float(~k);
}
__device__ __forceinline__ float blockReduce256(float v, float* red8) {
    int tid = threadIdx.x;
    #pragma unroll
    for (int off = 16; off; off >>= 1) v += __shfl_down_sync(0xffffffffu, v, off);
    if ((tid & 31) == 0) red8[tid >> 5] = v;
    __syncthreads();
    if (tid == 0) {
        float t = 0.f;
        #pragma unroll
        for (int w = 0; w < 8; w++) t += red8[w];
        red8[0] = t;
    }
    __syncthreads();
    float r = red8[0];
    __syncthreads();
    return r;
}

// ---------------- kernel 1: row L2 normalize -> bf16 ----------------
__global__ void k_normalize(const float* __restrict__ h1, const float* __restrict__ h2) {
    int r = blockIdx.x;
    if (r == 0 && threadIdx.x == 0) g_acc = 0.0;   // stream-ordered zero for select's atomics
    const float* src = (r < NROW) ? (h1 + (size_t)r * DIM)
                                  : (h2 + (size_t)(r - NROW) * DIM);
    int tid = threadIdx.x;                 // 128 threads, 4 floats each
    float4 v = ((const float4*)src)[tid];
    float ss = v.x * v.x + v.y * v.y + v.z * v.z + v.w * v.w;
    __shared__ float red[4];
    #pragma unroll
    for (int off = 16; off; off >>= 1) ss += __shfl_down_sync(0xffffffffu, ss, off);
    if ((tid & 31) == 0) red[tid >> 5] = ss;
    __syncthreads();
    if (tid == 0) {
        float t = red[0] + red[1] + red[2] + red[3];
        red[0] = 1.0f / fmaxf(sqrtf(t), 1e-12f);
    }
    __syncthreads();
    float rinv = red[0];
    __nv_bfloat162 p0 = __floats2bfloat162_rn(v.x * rinv, v.y * rinv);
    __nv_bfloat162 p1 = __floats2bfloat162_rn(v.z * rinv, v.w * rinv);
    __nv_bfloat162* dst = (__nv_bfloat162*)(g_Zb + (size_t)r * DIM);
    dst[tid * 2]     = p0;
    dst[tid * 2 + 1] = p1;
}

// ---------------- kernel 2: S = Z Z^T via mma.sync bf16 ----------------
// CTA: 128x128 tile, BK=32, 256 threads = 8 warps (4 in M x 2 in N), warp 32x64.
// SMEM rows padded to 80B (32 bf16 + 8 pad): bank group = 20*row mod 32 -> 8-row
// ldmatrix phases and cp.async stores are conflict-free. 3-stage cp.async ring.
#define ROWB     80
#define TILE_AB  10240                 // 128 rows * 80B
#define STAGE_B  20480                 // A + B
#define NSTAGE   3
#define NKT      16                    // 512 / 32

__device__ __forceinline__ void load_stage(uint32_t sBase, int stage, int kt,
                                           int bm, int bn, int tid) {
    const uint32_t st = sBase + stage * STAGE_B;
    const int k0 = kt * 32;
    #pragma unroll
    for (int i = 0; i < 4; i++) {
        int id  = tid + i * 256;           // 0..1023
        int row = (id & 511) >> 2;         // 0..127
        int c   = id & 3;                  // 16B chunk
        int grow = (id < 512) ? (bm + row) : (bn + row);
        const void* g = g_Zb + (size_t)grow * DIM + k0 + c * 8;
        uint32_t s = st + (id < 512 ? 0 : TILE_AB) + row * ROWB + c * 16;
        cp_async16(s, g);
    }
}

__global__ void __launch_bounds__(256, 2) k_gemm() {
    extern __shared__ char dsm[];
    const int tid = threadIdx.x;
    const int wid = tid >> 5, l = tid & 31;
    const int bm = blockIdx.y * 128, bn = blockIdx.x * 128;
    const int wm = (wid & 3) * 32;         // warp M offset
    const int wn = (wid >> 2) * 64;        // warp N offset
    const uint32_t sBase = smem_u32(dsm);

    float acc[2][8][4];
    #pragma unroll
    for (int mi = 0; mi < 2; mi++)
        #pragma unroll
        for (int ni = 0; ni < 8; ni++)
            #pragma unroll
            for (int q = 0; q < 4; q++) acc[mi][ni][q] = 0.f;

    // prologue: stages 0,1
    load_stage(sBase, 0, 0, bm, bn, tid); cp_commit();
    load_stage(sBase, 1, 1, bm, bn, tid); cp_commit();

    // precomputed lane address pieces
    const uint32_t aRow = (l & 15);
    const uint32_t aChk = (l >> 4);                    // 0/1
    const uint32_t bRow = ((l >> 4) & 1) * 8 + (l & 7);
    const uint32_t bChk = (l >> 3) & 1;

    for (int kt = 0; kt < NKT; kt++) {
        if (kt < NKT - 2) cp_wait<1>(); else cp_wait<0>();
        __syncthreads();
        if (kt + 2 < NKT) {
            load_stage(sBase, (kt + 2) % NSTAGE, kt + 2, bm, bn, tid);
            cp_commit();
        }
        const uint32_t aB = sBase + (kt % NSTAGE) * STAGE_B + wm * ROWB;
        const uint32_t bB = sBase + (kt % NSTAGE) * STAGE_B + TILE_AB + wn * ROWB;
        #pragma unroll
        for (int ks = 0; ks < 2; ks++) {
            uint32_t a[2][4];
            #pragma unroll
            for (int mi = 0; mi < 2; mi++)
                ldm_x4(aB + (mi * 16 + aRow) * ROWB + (ks * 2 + aChk) * 16,
                       a[mi][0], a[mi][1], a[mi][2], a[mi][3]);
            uint32_t b[4][4];
            #pragma unroll
            for (int nj = 0; nj < 4; nj++)
                ldm_x4(bB + (nj * 16 + bRow) * ROWB + (ks * 2 + bChk) * 16,
                       b[nj][0], b[nj][1], b[nj][2], b[nj][3]);
            #pragma unroll
            for (int mi = 0; mi < 2; mi++)
                #pragma unroll
                for (int ni = 0; ni < 8; ni++)
                    mma_bf16(acc[mi][ni][0], acc[mi][ni][1], acc[mi][ni][2], acc[mi][ni][3],
                             a[mi][0], a[mi][1], a[mi][2], a[mi][3],
                             b[ni >> 1][(ni & 1) * 2], b[ni >> 1][(ni & 1) * 2 + 1]);
        }
        __syncthreads();
    }

    // epilogue: lane l holds rows m+(l>>2), m+8+(l>>2); cols n+(l&3)*2 (+1)
    const int r0 = bm + wm + (l >> 2);
    const int c0 = bn + wn + (l & 3) * 2;
    #pragma unroll
    for (int mi = 0; mi < 2; mi++) {
        #pragma unroll
        for (int ni = 0; ni < 8; ni++) {
            float* p0 = g_S + (size_t)(r0 + mi * 16) * R2 + c0 + ni * 8;
            float* p1 = p0 + (size_t)8 * R2;
            p0[0] = acc[mi][ni][0]; p0[1] = acc[mi][ni][1];
            p1[0] = acc[mi][ni][2]; p1[1] = acc[mi][ni][3];
        }
    }
}

// ---------------- kernel 3: per-row trim + exp-sum (exact radix select) ----------------
__global__ void __launch_bounds__(256) k_select() {
    const int r   = blockIdx.x;
    const int tid = threadIdx.x;     // 256 threads
    __shared__ unsigned su[R2];      // 32 KB row keys
    __shared__ unsigned hist[256];
    __shared__ unsigned sc[256];
    __shared__ float    redf[8];
    __shared__ unsigned s_sel, s_k;

    const float* row = g_S + (size_t)r * R2;
    float tot = 0.f;
    #pragma unroll
    for (int j = 0; j < 8; j++) {
        int i4 = tid + j * 256;
        float4 v = ((const float4*)row)[i4];
        tot += fast_exp2x(v.x) + fast_exp2x(v.y) + fast_exp2x(v.z) + fast_exp2x(v.w);
        su[i4 * 4 + 0] = f2k(v.x);
        su[i4 * 4 + 1] = f2k(v.y);
        su[i4 * 4 + 2] = f2k(v.z);
        su[i4 * 4 + 3] = f2k(v.w);
    }
    tot = blockReduce256(tot, redf);

    // ---- radix select: 409th-largest key ----
    unsigned prefix = 0, mask = 0, k = THR;
    #pragma unroll
    for (int pass = 0; pass < 4; pass++) {
        int shift = 24 - 8 * pass;
        hist[tid] = 0; __syncthreads();
        for (int i = tid; i < R2; i += 256) {
            unsigned key = su[i];
            if ((key & mask) == prefix) atomicAdd(&hist[(key >> shift) & 255u], 1u);
        }
        __syncthreads();
        sc[tid] = hist[tid]; __syncthreads();
        for (int off = 1; off < 256; off <<= 1) {   // inclusive suffix scan
            unsigned add = (tid + off < 256) ? sc[tid + off] : 0u;
            __syncthreads();
            sc[tid] += add;
            __syncthreads();
        }
        unsigned ge = sc[tid];
        unsigned gt = (tid < 255) ? sc[tid + 1] : 0u;
        if (ge >= k && gt < k) { s_sel = (unsigned)tid; s_k = k - gt; }
        __syncthreads();
        prefix |= s_sel << shift;
        mask   |= 255u  << shift;
        k = s_k;
        __syncthreads();
    }
    const unsigned Khi = prefix, dup_hi = k;

    // ---- radix select: 409th-smallest key ----
    prefix = 0; mask = 0; k = THR;
    #pragma unroll
    for (int pass = 0; pass < 4; pass++) {
        int shift = 24 - 8 * pass;
        hist[tid] = 0; __syncthreads();
        for (int i = tid; i < R2; i += 256) {
            unsigned key = su[i];
            if ((key & mask) == prefix) atomicAdd(&hist[(key >> shift) & 255u], 1u);
        }
        __syncthreads();
        sc[tid] = hist[tid]; __syncthreads();
        for (int off = 1; off < 256; off <<= 1) {   // inclusive prefix scan
            unsigned add = (tid >= off) ? sc[tid - off] : 0u;
            __syncthreads();
            sc[tid] += add;
            __syncthreads();
        }
        unsigned le = sc[tid];
        unsigned lt = (tid > 0) ? sc[tid - 1] : 0u;
        if (le >= k && lt < k) { s_sel = (unsigned)tid; s_k = k - lt; }
        __syncthreads();
        prefix |= s_sel << shift;
        mask   |= 255u  << shift;
        k = s_k;
        __syncthreads();
    }
    const unsigned Klo = prefix, dup_lo = k;

    // ---- tail sums (exact, tie-correct) ----
    float ts = 0.f, bs = 0.f;
    for (int i = tid; i < R2; i += 256) {
        unsigned key = su[i];
        if (key > Khi) ts += fast_exp2x(k2f(key));
        if (key < Klo) bs += fast_exp2x(k2f(key));
    }
    ts = blockReduce256(ts, redf);
    bs = blockReduce256(bs, redf);

    if (tid == 0) {
        float top = ts + (float)dup_hi * fast_exp2x(k2f(Khi));
        float bot = bs + (float)dup_lo * fast_exp2x(k2f(Klo));
        double contrib = 0.5 * (double)logf(tot - top - bot);
        if (r < NROW) contrib -= 2.0 * (double)row[NROW + r];   // -log(pos) for this pair
        atomicAdd(&g_acc, contrib);
    }
}

// ---------------- kernel 4: final scalar ----------------
__global__ void k_final(float* __restrict__ out) {
    out[0] = (float)(g_acc / (double)NROW);
}

// ---------------- launch ----------------
extern "C" void kernel_launch(void* const* d_in, const int* in_sizes, int n_in,
                              void* d_out, int out_size) {
    const float* h1 = (const float*)d_in[0];
    const float* h2 = (const float*)d_in[1];
    (void)in_sizes; (void)n_in; (void)out_size;

    cudaFuncSetAttribute(k_gemm, cudaFuncAttributeMaxDynamicSharedMemorySize,
                         NSTAGE * STAGE_B);

    k_normalize<<<R2, 128>>>(h1, h2);
    dim3 g(R2 / 128, R2 / 128);
    k_gemm<<<g, 256, NSTAGE * STAGE_B>>>();
    k_select<<<R2, 256>>>();
    k_final<<<1, 1>>>((float*)d_out);
}